// round 12
// baseline (speedup 1.0000x reference)
#include <cuda_runtime.h>
#include <math.h>
#include <float.h>
#include <stdint.h>

__device__ float g_a1[33554432];
__device__ float g_a2[8388608];
__device__ float g_a3[2097152];
__device__ float g_z [2097152];
__device__ float g_zq[2097152];
__device__ float g_d1[2097152];
__device__ float g_dmin[32768];
__device__ float g_e2[512];
__device__ float g_pw2[16*64*64];
__device__ float g_pw3[16*64*64];
__device__ float g_pe4[9*64*64];
__device__ float g_pd1[9*64*64];
__device__ float g_pt1[16*64*64];
__device__ float g_pt2[16*64*64];

__device__ __forceinline__ float* g_buf(int s) {
    switch (s) {
        case 1: return g_a1; case 2: return g_a2; case 3: return g_a3;
        case 4: return g_z;  case 5: return g_zq; case 6: return g_d1;
    }
    return nullptr;
}
__device__ __forceinline__ float* g_pbuf(int s) {
    switch (s) {
        case 1: return g_pw2; case 2: return g_pw3; case 3: return g_pe4;
        case 4: return g_pd1; case 5: return g_pt1; case 6: return g_pt2;
    }
    return nullptr;
}

__device__ __forceinline__ unsigned long long pk2(float x, float y) {
    unsigned long long r;
    asm("mov.b64 %0, {%1,%2};" : "=l"(r) : "f"(x), "f"(y));
    return r;
}
__device__ __forceinline__ float2 upk2(unsigned long long v) {
    float2 r;
    asm("mov.b64 {%0,%1}, %2;" : "=f"(r.x), "=f"(r.y) : "l"(v));
    return r;
}
__device__ __forceinline__ void ffma2(unsigned long long& d, unsigned long long a,
                                      unsigned long long b) {
    asm("fma.rn.f32x2 %0, %1, %2, %3;" : "=l"(d) : "l"(a), "l"(b), "l"(d));
}
__device__ __forceinline__ void cp4(uint32_t dst, const float* src, bool p) {
    int sz = p ? 4 : 0;
    asm volatile("cp.async.ca.shared.global [%0], [%1], 4, %2;\n"
                 :: "r"(dst), "l"(src), "r"(sz));
}
__device__ __forceinline__ void cp16(uint32_t dst, const float* src) {
    asm volatile("cp.async.ca.shared.global [%0], [%1], 16;\n" :: "r"(dst), "l"(src));
}
__device__ __forceinline__ void cp_commit() { asm volatile("cp.async.commit_group;"); }
__device__ __forceinline__ void cp_wait0()  { asm volatile("cp.async.wait_group 0;"); }
__device__ __forceinline__ float tf32r(float x) {
    float r; asm("cvt.rna.tf32.f32 %0, %1;" : "=f"(r) : "f"(x)); return r;
}
__device__ __forceinline__ uint32_t fbits(float f) { return __float_as_uint(f); }
__device__ __forceinline__ void mma8(float* d, uint32_t a0, uint32_t a1, uint32_t a2,
                                     uint32_t a3, uint32_t b0, uint32_t b1) {
    asm volatile(
        "mma.sync.aligned.m16n8k8.row.col.f32.tf32.tf32.f32 "
        "{%0,%1,%2,%3},{%4,%5,%6,%7},{%8,%9},{%0,%1,%2,%3};"
        : "+f"(d[0]), "+f"(d[1]), "+f"(d[2]), "+f"(d[3])
        : "r"(a0), "r"(a1), "r"(a2), "r"(a3), "r"(b0), "r"(b1));
}
// column permutation so a thread's 8 B elements (cols nt*8+g) are contiguous
__device__ __forceinline__ int bperm(int co) { return ((co & 7) << 3) | (co >> 3); }

__global__ void k_prep_oihw(const float* __restrict__ w, int taps, int dsel, int rnd)
{
    float* dst = g_pbuf(dsel);
    int bi = blockIdx.x;
    int ci = bi / taps, tap = bi - ci * taps;
    int co = threadIdx.x;
    float v = w[(co * 64 + ci) * taps + tap];
    dst[(tap * 64 + ci) * 64 + bperm(co)] = rnd ? tf32r(v) : v;
}
__global__ void k_prep_t(const float* __restrict__ w, int dsel, int rnd)
{
    float* dst = g_pbuf(dsel);
    int bi = blockIdx.x;
    int ci = bi & 63, tap = (bi >> 6) & 3, cls = bi >> 8;
    int dy = cls >> 1, dx = cls & 1, a = tap >> 1, bb = tap & 1;
    int ky = 1 - dy + 2 * a, kx = 1 - dx + 2 * bb;
    int co = threadIdx.x;
    float v = w[(ci * 64 + co) * 16 + ky * 4 + kx];
    dst[((cls * 4 + tap) * 64 + ci) * 64 + bperm(co)] = rnd ? tf32r(v) : v;
}

// unified tf32 mma conv. ctype: 0=3x3s1p1, 1=convT parity class, 2=4x4s2p1.
// split=1: 3xTF32 (fp32-accurate). 32-ci stages, XOR-swizzled smem, vector B.
__global__ __launch_bounds__(128) void k_mconv(int in_sel, int wsel,
    const float* __restrict__ bias, int out_sel, int Win, int Wp, int wsh,
    int ctype, int do_relu, int split)
{
    __shared__ __align__(16) float sA[2][32 * 128];
    __shared__ __align__(16) float sB[2][32 * 64];
    const float* in = g_buf(in_sel);
    const float* wp = g_pbuf(wsel);
    float* out = g_buf(out_sel);
    const int tid = threadIdx.x, lane = tid & 31, w = tid >> 5;
    const int g = lane >> 2, tq = lane & 3;
    const int b = blockIdx.y, cls = blockIdx.z, dy = cls >> 1, dx = cls & 1;
    const int gp = blockIdx.x * 128 + tid;
    const int py = gp >> wsh, px = gp & (Wp - 1);
    const size_t HW = (size_t)Win * Win;
    const float* inb = in + (size_t)b * 64 * HW;
    uint32_t sa0 = (uint32_t)__cvta_generic_to_shared(&sA[0][0]);
    uint32_t sb0 = (uint32_t)__cvta_generic_to_shared(&sB[0][0]);
    const int ntap = (ctype == 0) ? 9 : (ctype == 1 ? 4 : 16);
    const int nst = ntap * 2;

    float acc[16][4];
#pragma unroll
    for (int i = 0; i < 16; i++)
#pragma unroll
        for (int j = 0; j < 4; j++) acc[i][j] = 0.f;

    auto stage = [&](int s, int buf) {
        int tap = s >> 1, chunk = s & 1;
        int iy, ix;
        if (ctype == 0)      { iy = py + tap / 3 - 1;        ix = px + tap % 3 - 1; }
        else if (ctype == 1) { iy = py + dy - (tap >> 1);    ix = px + dx - (tap & 1); }
        else                 { iy = 2 * py + (tap >> 2) - 1; ix = 2 * px + (tap & 3) - 1; }
        bool ok = (unsigned)iy < (unsigned)Win && (unsigned)ix < (unsigned)Win;
        const float* src = inb + (size_t)(chunk * 32) * HW +
                           (ok ? (size_t)iy * Win + ix : 0);
        uint32_t dA = sa0 + buf * 16384;
#pragma unroll
        for (int j = 0; j < 32; j++)
            cp4(dA + (j * 128 + (tid ^ ((j & 3) << 3))) * 4, src + (size_t)j * HW, ok);
        int tapidx = (ctype == 1) ? cls * 4 + tap : tap;
        const float* ws = wp + ((size_t)tapidx * 64 + chunk * 32) * 64;
        uint32_t dB = sb0 + buf * 8192;
#pragma unroll
        for (int it = 0; it < 4; it++) {
            int idx = it * 128 + tid;
            int ci = idx >> 4, cog = (idx & 15) * 4;
            cp16(dB + (ci * 64 + (cog ^ ((ci & 3) << 3))) * 4, ws + ci * 64 + cog);
        }
    };
    auto comp = [&](const float* A, const float* B) {
        const int swz = tq << 3;
#pragma unroll
        for (int k2 = 0; k2 < 4; k2++) {
            int k0 = k2 * 8;
            float af[2][4];
#pragma unroll
            for (int mt = 0; mt < 2; mt++) {
                int m0 = w * 32 + mt * 16 + g;
                af[mt][0] = A[(k0 + tq) * 128 + (m0 ^ swz)];
                af[mt][1] = A[(k0 + tq) * 128 + ((m0 + 8) ^ swz)];
                af[mt][2] = A[(k0 + tq + 4) * 128 + (m0 ^ swz)];
                af[mt][3] = A[(k0 + tq + 4) * 128 + ((m0 + 8) ^ swz)];
            }
            uint32_t ah[2][4], al[2][4];
#pragma unroll
            for (int mt = 0; mt < 2; mt++)
#pragma unroll
                for (int i = 0; i < 4; i++) {
                    if (split) {
                        float h = tf32r(af[mt][i]);
                        ah[mt][i] = fbits(h);
                        al[mt][i] = fbits(af[mt][i] - h);
                    } else ah[mt][i] = fbits(af[mt][i]);
                }
            // vector B: permuted cols make this thread's 8 elements contiguous
            int rb0 = (k0 + tq) * 64 + ((g ^ tq) << 3);
            int rb1 = (k0 + tq + 4) * 64 + ((g ^ tq) << 3);
            float4 q0 = *(const float4*)&B[rb0], q1 = *(const float4*)&B[rb0 + 4];
            float4 q2 = *(const float4*)&B[rb1], q3 = *(const float4*)&B[rb1 + 4];
            float br0[8] = {q0.x, q0.y, q0.z, q0.w, q1.x, q1.y, q1.z, q1.w};
            float br1[8] = {q2.x, q2.y, q2.z, q2.w, q3.x, q3.y, q3.z, q3.w};
#pragma unroll
            for (int nt = 0; nt < 8; nt++) {
                float b0f = br0[nt], b1f = br1[nt];
                if (!split) {
                    uint32_t b0 = fbits(b0f), b1 = fbits(b1f);
                    mma8(acc[nt],     ah[0][0], ah[0][1], ah[0][2], ah[0][3], b0, b1);
                    mma8(acc[8 + nt], ah[1][0], ah[1][1], ah[1][2], ah[1][3], b0, b1);
                } else {
                    float h0 = tf32r(b0f), h1 = tf32r(b1f);
                    uint32_t bh0 = fbits(h0), bh1 = fbits(h1);
                    uint32_t bl0 = fbits(b0f - h0), bl1 = fbits(b1f - h1);
#pragma unroll
                    for (int mt = 0; mt < 2; mt++) {
                        float* ac = acc[mt * 8 + nt];
                        mma8(ac, ah[mt][0], ah[mt][1], ah[mt][2], ah[mt][3], bl0, bl1);
                        mma8(ac, al[mt][0], al[mt][1], al[mt][2], al[mt][3], bh0, bh1);
                        mma8(ac, ah[mt][0], ah[mt][1], ah[mt][2], ah[mt][3], bh0, bh1);
                    }
                }
            }
        }
    };

    stage(0, 0); cp_commit(); cp_wait0(); __syncthreads();
    for (int s = 0; s < nst; s++) {
        int buf = s & 1;
        if (s + 1 < nst) { stage(s + 1, buf ^ 1); cp_commit(); }
        comp(sA[buf], sB[buf]);
        if (s + 1 < nst) cp_wait0();
        __syncthreads();
    }

    const size_t HP = (size_t)Wp * Wp;
#pragma unroll
    for (int mt = 0; mt < 2; mt++)
#pragma unroll
        for (int nt = 0; nt < 8; nt++) {
            int c0 = nt * 8 + 2 * tq;
            float bv0 = bias[c0], bv1 = bias[c0 + 1];
            const float* A = acc[mt * 8 + nt];
#pragma unroll
            for (int h = 0; h < 2; h++) {
                int r = w * 32 + mt * 16 + g + h * 8;
                int gp2 = blockIdx.x * 128 + r;
                int qy = gp2 >> wsh, qx = gp2 & (Wp - 1);
                float v0 = A[2 * h] + bv0, v1 = A[2 * h + 1] + bv1;
                if (do_relu) { v0 = fmaxf(v0, 0.f); v1 = fmaxf(v1, 0.f); }
                if (ctype == 1) {
                    size_t o = (((size_t)b * 64 + c0) * (2 * Wp) + 2 * qy + dy) *
                               (size_t)(2 * Wp) + 2 * qx + dx;
                    out[o] = v0;
                    out[o + 4 * HP] = v1;
                } else {
                    size_t o = (((size_t)b * 64 + c0) * Wp + qy) * (size_t)Wp + qx;
                    out[o] = v0;
                    out[o + HP] = v1;
                }
            }
        }
}

__global__ void k_conv1(const float* __restrict__ x, const float* __restrict__ w,
                        const float* __restrict__ bias)
{
    __shared__ unsigned long long sw2[512];
    __shared__ float sb[64];
    const int tid = threadIdx.x;
    for (int i = tid; i < 512; i += 256) {
        int co2 = i >> 4, t = i & 15;
        sw2[i] = pk2(w[(2 * co2) * 16 + t], w[(2 * co2 + 1) * 16 + t]);
    }
    if (tid < 64) sb[tid] = bias[tid];
    __syncthreads();
    const int gid = blockIdx.x * 256 + tid;
    const int ox = gid & 255, oy = (gid >> 8) & 255, b = gid >> 16;
    const int iy0 = oy * 2 - 1, ix0 = ox * 2 - 1;
    const float* xb = x + (size_t)b * 262144;
    unsigned long long vp[16];
#pragma unroll
    for (int ky = 0; ky < 4; ky++)
#pragma unroll
        for (int kx = 0; kx < 4; kx++) {
            int iy = iy0 + ky, ix = ix0 + kx;
            float t = 0.f;
            if ((unsigned)iy < 512u && (unsigned)ix < 512u) t = xb[iy * 512 + ix];
            vp[ky * 4 + kx] = pk2(t, t);
        }
    float* ob = g_a1 + (size_t)b * 64 * 65536 + oy * 256 + ox;
#pragma unroll 4
    for (int co2 = 0; co2 < 32; co2++) {
        unsigned long long a2 = 0ull;
#pragma unroll
        for (int t = 0; t < 16; t++) ffma2(a2, vp[t], sw2[co2 * 16 + t]);
        float2 u = upk2(a2);
        ob[(size_t)(2 * co2) * 65536]     = fmaxf(u.x + sb[2 * co2], 0.f);
        ob[(size_t)(2 * co2 + 1) * 65536] = fmaxf(u.y + sb[2 * co2 + 1], 0.f);
    }
}

// final convT 64->1 + sigmoid. Grid MUST be (8,16,8).
__global__ __launch_bounds__(128) void k_cto(const float* __restrict__ w,
    const float* __restrict__ bias, float* __restrict__ out)
{
    __shared__ float s_t[2][18 * 35];
    __shared__ float s_w[1024];
    const int tid = threadIdx.x, tx = tid & 7, ty = tid >> 3;
    const int b = blockIdx.z;
    const int py0 = blockIdx.y * 16, qx0 = blockIdx.x * 32;
    const float* inb = g_a1 + (size_t)b * 64 * 65536;
    uint32_t st0 = (uint32_t)__cvta_generic_to_shared(&s_t[0][0]);
    for (int i = tid; i < 1024; i += 128) s_w[i] = w[i];

    auto stage = [&](int ci, int buf) {
        const float* ic = inb + (size_t)ci * 65536;
        for (int i = tid; i < 630; i += 128) {
            int r = i / 35, cl = i - r * 35;
            int iy = py0 - 1 + r, ix = qx0 - 1 + cl;
            bool ok = cl < 34 && (unsigned)iy < 256u && (unsigned)ix < 256u;
            cp4(st0 + (buf * 630 + i) * 4, ic + (ok ? iy * 256 + ix : 0), ok);
        }
    };

    unsigned long long acc[8];
#pragma unroll
    for (int i = 0; i < 8; i++) acc[i] = 0ull;

    stage(0, 0); cp_commit(); cp_wait0(); __syncthreads();
    for (int ci = 0; ci < 64; ci++) {
        int buf = ci & 1;
        if (ci + 1 < 64) { stage(ci + 1, buf ^ 1); cp_commit(); }
        const float* T = s_t[buf];
        float v[3][6];
#pragma unroll
        for (int r = 0; r < 3; r++)
#pragma unroll
            for (int c = 0; c < 6; c++) v[r][c] = T[(ty + r) * 35 + 4 * tx + c];
        unsigned long long vp[3][3][2];
#pragma unroll
        for (int rr = 0; rr < 3; rr++)
#pragma unroll
            for (int cc = 0; cc < 3; cc++)
#pragma unroll
                for (int jp = 0; jp < 2; jp++)
                    vp[rr][cc][jp] = pk2(v[rr][2 * jp + cc], v[rr][2 * jp + cc + 1]);
#pragma unroll
        for (int dy = 0; dy < 2; dy++)
#pragma unroll
            for (int dx = 0; dx < 2; dx++)
#pragma unroll
                for (int a = 0; a < 2; a++)
#pragma unroll
                    for (int bb = 0; bb < 2; bb++) {
                        float wv = s_w[ci * 16 + (1 - dy + 2 * a) * 4 + (1 - dx + 2 * bb)];
                        unsigned long long w2 = pk2(wv, wv);
                        int rr = 1 + dy - a, cc = 1 + dx - bb;
                        ffma2(acc[(dy * 2 + dx) * 2 + 0], vp[rr][cc][0], w2);
                        ffma2(acc[(dy * 2 + dx) * 2 + 1], vp[rr][cc][1], w2);
                    }
        if (ci + 1 < 64) cp_wait0();
        __syncthreads();
    }
    float bv = bias[0];
#pragma unroll
    for (int dy = 0; dy < 2; dy++)
#pragma unroll
        for (int dx = 0; dx < 2; dx++)
#pragma unroll
            for (int jp = 0; jp < 2; jp++) {
                float2 u = upk2(acc[(dy * 2 + dx) * 2 + jp]);
#pragma unroll
                for (int l = 0; l < 2; l++) {
                    int j = 2 * jp + l;
                    int oy = 2 * (py0 + ty) + dy, ox = 2 * (qx0 + 4 * tx + j) + dx;
                    float s = (l ? u.y : u.x) + bv;
                    s = 1.f / (1.f + expf(-s));
                    out[((size_t)b * 512 + oy) * 512 + ox] = s;
                }
            }
}

__global__ void k_e2(const float* __restrict__ cb)
{
    int k = threadIdx.x;
    float s = 0.f;
    for (int c = 0; c < 64; c++) { float v = cb[k * 64 + c]; s += v * v; }
    g_e2[k] = s;
}

// VQ: 64 positions x 512 codes per block, FFMA2-blocked
__global__ __launch_bounds__(128) void k_vq(const float* __restrict__ cb)
{
    __shared__ float s_z[64 * 64];
    __shared__ float s_cb[2][64 * 66];
    __shared__ float s_z2[64];
    __shared__ float s_bd[64 * 8];
    __shared__ int   s_bk[64 * 8];
    __shared__ int   s_kf[64];
    const int tid = threadIdx.x;
    const int pos0 = blockIdx.x * 64;
    const int b = pos0 >> 12, hw0 = pos0 & 4095;
    const float* zb = g_z + (size_t)b * 262144;
    uint32_t sz0 = (uint32_t)__cvta_generic_to_shared(&s_z[0]);
    uint32_t sc0 = (uint32_t)__cvta_generic_to_shared(&s_cb[0][0]);

    for (int i = tid; i < 4096; i += 128) {
        int c = i >> 6, p = i & 63;
        cp4(sz0 + (c * 64 + p) * 4, zb + (size_t)c * 4096 + hw0 + p, true);
    }
    for (int i = tid; i < 4096; i += 128) {
        int code = i >> 6, c = i & 63;
        cp4(sc0 + (c * 66 + code) * 4, cb + i, true);
    }
    cp_commit(); cp_wait0(); __syncthreads();
    if (tid < 64) {
        float s = 0.f;
        for (int c = 0; c < 64; c++) { float t = s_z[c * 64 + tid]; s += t * t; }
        s_z2[tid] = s;
    }
    const int pg = tid & 15, cg = tid >> 4;
    float bd[4] = {FLT_MAX, FLT_MAX, FLT_MAX, FLT_MAX};
    int bk[4] = {0, 0, 0, 0};

    for (int chunk = 0; chunk < 8; chunk++) {
        int buf = chunk & 1;
        if (chunk < 7) {
            for (int i = tid; i < 4096; i += 128) {
                int code = i >> 6, c = i & 63;
                cp4(sc0 + ((buf ^ 1) * 4224 + c * 66 + code) * 4,
                    cb + (chunk + 1) * 4096 + i, true);
            }
            cp_commit();
        }
        unsigned long long acc[4][4];
#pragma unroll
        for (int j = 0; j < 4; j++)
#pragma unroll
            for (int jj = 0; jj < 4; jj++) acc[j][jj] = 0ull;
        const float* C = &s_cb[buf][0];
#pragma unroll 4
        for (int c = 0; c < 64; c++) {
            unsigned long long zz[4];
#pragma unroll
            for (int j = 0; j < 4; j++) {
                float zv = s_z[c * 64 + pg + 16 * j];
                zz[j] = pk2(zv, zv);
            }
            unsigned long long wv[4];
#pragma unroll
            for (int jj = 0; jj < 4; jj++)
                wv[jj] = *(const unsigned long long*)&C[c * 66 + cg * 8 + 2 * jj];
#pragma unroll
            for (int j = 0; j < 4; j++)
#pragma unroll
                for (int jj = 0; jj < 4; jj++) ffma2(acc[j][jj], zz[j], wv[jj]);
        }
#pragma unroll
        for (int jj = 0; jj < 4; jj++) {
            int k0 = chunk * 64 + cg * 8 + 2 * jj;
            float ea = g_e2[k0], ebv = g_e2[k0 + 1];
#pragma unroll
            for (int j = 0; j < 4; j++) {
                float2 d2 = upk2(acc[j][jj]);
                float d0 = ea - 2.f * d2.x, d1 = ebv - 2.f * d2.y;
                if (d0 < bd[j]) { bd[j] = d0; bk[j] = k0; }
                if (d1 < bd[j]) { bd[j] = d1; bk[j] = k0 + 1; }
            }
        }
        if (chunk < 7) cp_wait0();
        __syncthreads();
    }
#pragma unroll
    for (int j = 0; j < 4; j++) {
        int p = pg + 16 * j;
        s_bd[p * 8 + cg] = bd[j];
        s_bk[p * 8 + cg] = bk[j];
    }
    __syncthreads();
    if (tid < 64) {
        float best = FLT_MAX; int kb = 0;
        for (int c = 0; c < 8; c++) {
            float d = s_bd[tid * 8 + c]; int k = s_bk[tid * 8 + c];
            if (d < best || (d == best && k < kb)) { best = d; kb = k; }
        }
        g_dmin[pos0 + tid] = s_z2[tid] + best;
        s_kf[tid] = kb;
    }
    __syncthreads();
    float* zqb = g_zq + (size_t)b * 262144;
    for (int i = tid; i < 4096; i += 128) {
        int c = i >> 6, p = i & 63;
        zqb[(size_t)c * 4096 + hw0 + p] = cb[s_kf[p] * 64 + c];
    }
}

__global__ void k_loss(float* __restrict__ out_loss)
{
    __shared__ float sm[1024];
    int tid = threadIdx.x;
    float s = 0.f;
    for (int i = tid; i < 32768; i += 1024) s += g_dmin[i];
    sm[tid] = s;
    __syncthreads();
    for (int off = 512; off; off >>= 1) {
        if (tid < off) sm[tid] += sm[tid + off];
        __syncthreads();
    }
    if (tid == 0) out_loss[0] = sm[0] * (1.25f / 2097152.f);
}

extern "C" void kernel_launch(void* const* d_in, const int* in_sizes, int n_in,
                              void* d_out, int out_size)
{
    const float* x   = (const float*)d_in[0];
    const float* ew1 = (const float*)d_in[1];
    const float* eb1 = (const float*)d_in[2];
    const float* ew2 = (const float*)d_in[3];
    const float* eb2 = (const float*)d_in[4];
    const float* ew3 = (const float*)d_in[5];
    const float* eb3 = (const float*)d_in[6];
    const float* ew4 = (const float*)d_in[7];
    const float* eb4 = (const float*)d_in[8];
    const float* cb  = (const float*)d_in[9];
    const float* dw1 = (const float*)d_in[10];
    const float* db1 = (const float*)d_in[11];
    const float* tw1 = (const float*)d_in[12];
    const float* tb1 = (const float*)d_in[13];
    const float* tw2 = (const float*)d_in[14];
    const float* tb2 = (const float*)d_in[15];
    const float* tw3 = (const float*)d_in[16];
    const float* tb3 = (const float*)d_in[17];
    float* out = (float*)d_out;

    k_prep_oihw<<<64 * 16, 64>>>(ew2, 16, 1, 0);
    k_conv1<<<2048, 256>>>(x, ew1, eb1);
    k_prep_oihw<<<64 * 16, 64>>>(ew3, 16, 2, 0);
    k_prep_oihw<<<64 * 9, 64>>>(ew4, 9, 3, 0);
    k_prep_oihw<<<64 * 9, 64>>>(dw1, 9, 4, 1);
    k_mconv<<<dim3(128, 8, 1), 128>>>(1, 1, eb2, 2, 256, 128, 7, 2, 1, 1); // conv2
    k_prep_t<<<1024, 64>>>(tw1, 5, 1);
    k_prep_t<<<1024, 64>>>(tw2, 6, 1);
    k_e2<<<1, 512>>>(cb);
    k_mconv<<<dim3(32, 8, 1),  128>>>(2, 2, eb3, 3, 128, 64, 6, 2, 1, 1);  // conv3
    k_mconv<<<dim3(32, 8, 1),  128>>>(3, 3, eb4, 4, 64, 64, 6, 0, 0, 1);   // enc4

    k_vq<<<512, 128>>>(cb);
    k_loss<<<1, 1024>>>(out + (out_size - 1));

    k_mconv<<<dim3(32, 8, 1),  128>>>(5, 4, db1, 6, 64, 64, 6, 0, 1, 0);   // dec1
    k_mconv<<<dim3(32, 8, 4),  128>>>(6, 5, tb1, 2, 64, 64, 6, 1, 1, 0);   // convT1
    k_mconv<<<dim3(128, 8, 4), 128>>>(2, 6, tb2, 1, 128, 128, 7, 1, 1, 0); // convT2
    k_cto<<<dim3(8, 16, 8), 128>>>(tw3, tb3, out);
}

// round 13
// speedup vs baseline: 1.0437x; 1.0437x over previous
#include <cuda_runtime.h>
#include <math.h>
#include <float.h>
#include <stdint.h>

__device__ float g_a1[33554432];
__device__ float g_a2[8388608];
__device__ float g_a3[2097152];
__device__ float g_z [2097152];
__device__ float g_zq[2097152];
__device__ float g_d1[2097152];
__device__ float g_dmin[32768];
__device__ float g_e2[512];
__device__ float g_pw2[16*64*64];
__device__ float g_pw3[16*64*64];
__device__ float g_pe4[9*64*64];
__device__ float g_pd1[9*64*64];
__device__ float g_pt1[16*64*64];
__device__ float g_pt2[16*64*64];

__device__ __forceinline__ float* g_buf(int s) {
    switch (s) {
        case 1: return g_a1; case 2: return g_a2; case 3: return g_a3;
        case 4: return g_z;  case 5: return g_zq; case 6: return g_d1;
    }
    return nullptr;
}
__device__ __forceinline__ float* g_pbuf(int s) {
    switch (s) {
        case 1: return g_pw2; case 2: return g_pw3; case 3: return g_pe4;
        case 4: return g_pd1; case 5: return g_pt1; case 6: return g_pt2;
    }
    return nullptr;
}

__device__ __forceinline__ unsigned long long pk2(float x, float y) {
    unsigned long long r;
    asm("mov.b64 %0, {%1,%2};" : "=l"(r) : "f"(x), "f"(y));
    return r;
}
__device__ __forceinline__ float2 upk2(unsigned long long v) {
    float2 r;
    asm("mov.b64 {%0,%1}, %2;" : "=f"(r.x), "=f"(r.y) : "l"(v));
    return r;
}
__device__ __forceinline__ void ffma2(unsigned long long& d, unsigned long long a,
                                      unsigned long long b) {
    asm("fma.rn.f32x2 %0, %1, %2, %3;" : "=l"(d) : "l"(a), "l"(b), "l"(d));
}
__device__ __forceinline__ void cp4(uint32_t dst, const float* src, bool p) {
    int sz = p ? 4 : 0;
    asm volatile("cp.async.ca.shared.global [%0], [%1], 4, %2;\n"
                 :: "r"(dst), "l"(src), "r"(sz));
}
__device__ __forceinline__ void cp16(uint32_t dst, const float* src) {
    asm volatile("cp.async.ca.shared.global [%0], [%1], 16;\n" :: "r"(dst), "l"(src));
}
__device__ __forceinline__ void cp_commit() { asm volatile("cp.async.commit_group;"); }
__device__ __forceinline__ void cp_wait0()  { asm volatile("cp.async.wait_group 0;"); }
__device__ __forceinline__ float tf32r(float x) {
    float r; asm("cvt.rna.tf32.f32 %0, %1;" : "=f"(r) : "f"(x)); return r;
}
__device__ __forceinline__ uint32_t fbits(float f) { return __float_as_uint(f); }
__device__ __forceinline__ void mma8(float* d, uint32_t a0, uint32_t a1, uint32_t a2,
                                     uint32_t a3, uint32_t b0, uint32_t b1) {
    asm volatile(
        "mma.sync.aligned.m16n8k8.row.col.f32.tf32.tf32.f32 "
        "{%0,%1,%2,%3},{%4,%5,%6,%7},{%8,%9},{%0,%1,%2,%3};"
        : "+f"(d[0]), "+f"(d[1]), "+f"(d[2]), "+f"(d[3])
        : "r"(a0), "r"(a1), "r"(a2), "r"(a3), "r"(b0), "r"(b1));
}

// single fused prep: all weight transforms + codebook norms in one launch.
// blocks: [0,1024) pw2 | [1024,2048) pw3 | [2048,2624) pe4 | [2624,3200) pd1
//         [3200,4224) pt1 | [4224,5248) pt2 | [5248,5256) e2
__global__ void k_prep_all(const float* __restrict__ ew2, const float* __restrict__ ew3,
                           const float* __restrict__ ew4, const float* __restrict__ dw1,
                           const float* __restrict__ tw1, const float* __restrict__ tw2,
                           const float* __restrict__ cb)
{
    int bi = blockIdx.x, t = threadIdx.x;
    if (bi < 2048) {                       // OIHW taps=16, raw fp32 (split encoder)
        const float* w = bi < 1024 ? ew2 : ew3;
        float* dst = bi < 1024 ? g_pw2 : g_pw3;
        int b2 = bi & 1023;
        int ci = b2 >> 4, tap = b2 & 15;
        dst[(tap * 64 + ci) * 64 + t] = w[(t * 64 + ci) * 16 + tap];
    } else if (bi < 3200) {                // OIHW taps=9: pe4 raw, pd1 tf32
        int b2 = bi - 2048;
        const float* w = b2 < 576 ? ew4 : dw1;
        float* dst = b2 < 576 ? g_pe4 : g_pd1;
        int rnd = b2 < 576 ? 0 : 1;
        int b3 = b2 < 576 ? b2 : b2 - 576;
        int ci = b3 / 9, tap = b3 - ci * 9;
        float v = w[(t * 64 + ci) * 9 + tap];
        dst[(tap * 64 + ci) * 64 + t] = rnd ? tf32r(v) : v;
    } else if (bi < 5248) {                // convT weights, tf32
        int b2 = bi - 3200;
        const float* w = b2 < 1024 ? tw1 : tw2;
        float* dst = b2 < 1024 ? g_pt1 : g_pt2;
        int b3 = b2 & 1023;
        int ci = b3 & 63, tap = (b3 >> 6) & 3, cls = b3 >> 8;
        int dy = cls >> 1, dx = cls & 1, a = tap >> 1, bb = tap & 1;
        int ky = 1 - dy + 2 * a, kx = 1 - dx + 2 * bb;
        dst[((cls * 4 + tap) * 64 + ci) * 64 + t] = tf32r(w[(ci * 64 + t) * 16 + ky * 4 + kx]);
    } else {                               // codebook row norms
        int k = (bi - 5248) * 64 + t;
        float s = 0.f;
        for (int c = 0; c < 64; c++) { float v = cb[k * 64 + c]; s += v * v; }
        g_e2[k] = s;
    }
}

// unified tf32 mma conv. ctype: 0=3x3s1p1, 1=convT parity class, 2=4x4s2p1.
// split=1: 3xTF32 (fp32-accurate). 32-ci stages, XOR-swizzled smem, scalar B (conflict-free).
__global__ __launch_bounds__(128) void k_mconv(int in_sel, int wsel,
    const float* __restrict__ bias, int out_sel, int Win, int Wp, int wsh,
    int ctype, int do_relu, int split)
{
    __shared__ __align__(16) float sA[2][32 * 128];
    __shared__ __align__(16) float sB[2][32 * 64];
    const float* in = g_buf(in_sel);
    const float* wp = g_pbuf(wsel);
    float* out = g_buf(out_sel);
    const int tid = threadIdx.x, lane = tid & 31, w = tid >> 5;
    const int g = lane >> 2, tq = lane & 3;
    const int b = blockIdx.y, cls = blockIdx.z, dy = cls >> 1, dx = cls & 1;
    const int gp = blockIdx.x * 128 + tid;
    const int py = gp >> wsh, px = gp & (Wp - 1);
    const size_t HW = (size_t)Win * Win;
    const float* inb = in + (size_t)b * 64 * HW;
    uint32_t sa0 = (uint32_t)__cvta_generic_to_shared(&sA[0][0]);
    uint32_t sb0 = (uint32_t)__cvta_generic_to_shared(&sB[0][0]);
    const int ntap = (ctype == 0) ? 9 : (ctype == 1 ? 4 : 16);
    const int nst = ntap * 2;

    float acc[16][4];
#pragma unroll
    for (int i = 0; i < 16; i++)
#pragma unroll
        for (int j = 0; j < 4; j++) acc[i][j] = 0.f;

    auto stage = [&](int s, int buf) {
        int tap = s >> 1, chunk = s & 1;
        int iy, ix;
        if (ctype == 0)      { iy = py + tap / 3 - 1;        ix = px + tap % 3 - 1; }
        else if (ctype == 1) { iy = py + dy - (tap >> 1);    ix = px + dx - (tap & 1); }
        else                 { iy = 2 * py + (tap >> 2) - 1; ix = 2 * px + (tap & 3) - 1; }
        bool ok = (unsigned)iy < (unsigned)Win && (unsigned)ix < (unsigned)Win;
        const float* src = inb + (size_t)(chunk * 32) * HW +
                           (ok ? (size_t)iy * Win + ix : 0);
        uint32_t dA = sa0 + buf * 16384;
#pragma unroll
        for (int j = 0; j < 32; j++)
            cp4(dA + (j * 128 + (tid ^ ((j & 3) << 3))) * 4, src + (size_t)j * HW, ok);
        int tapidx = (ctype == 1) ? cls * 4 + tap : tap;
        const float* ws = wp + ((size_t)tapidx * 64 + chunk * 32) * 64;
        uint32_t dB = sb0 + buf * 8192;
#pragma unroll
        for (int it = 0; it < 4; it++) {
            int idx = it * 128 + tid;
            int ci = idx >> 4, cog = (idx & 15) * 4;
            cp16(dB + (ci * 64 + (cog ^ ((ci & 3) << 3))) * 4, ws + ci * 64 + cog);
        }
    };
    auto comp = [&](const float* A, const float* B) {
        const int swz = tq << 3;
#pragma unroll
        for (int k2 = 0; k2 < 4; k2++) {
            int k0 = k2 * 8;
            float af[2][4];
#pragma unroll
            for (int mt = 0; mt < 2; mt++) {
                int m0 = w * 32 + mt * 16 + g;
                af[mt][0] = A[(k0 + tq) * 128 + (m0 ^ swz)];
                af[mt][1] = A[(k0 + tq) * 128 + ((m0 + 8) ^ swz)];
                af[mt][2] = A[(k0 + tq + 4) * 128 + (m0 ^ swz)];
                af[mt][3] = A[(k0 + tq + 4) * 128 + ((m0 + 8) ^ swz)];
            }
            uint32_t ah[2][4], al[2][4];
#pragma unroll
            for (int mt = 0; mt < 2; mt++)
#pragma unroll
                for (int i = 0; i < 4; i++) {
                    if (split) {
                        float h = tf32r(af[mt][i]);
                        ah[mt][i] = fbits(h);
                        al[mt][i] = fbits(af[mt][i] - h);
                    } else ah[mt][i] = fbits(af[mt][i]);
                }
#pragma unroll
            for (int nt = 0; nt < 8; nt++) {
                int cc = (nt * 8 + g) ^ swz;
                float b0f = B[(k0 + tq) * 64 + cc];
                float b1f = B[(k0 + tq + 4) * 64 + cc];
                if (!split) {
                    uint32_t b0 = fbits(b0f), b1 = fbits(b1f);
                    mma8(acc[nt],     ah[0][0], ah[0][1], ah[0][2], ah[0][3], b0, b1);
                    mma8(acc[8 + nt], ah[1][0], ah[1][1], ah[1][2], ah[1][3], b0, b1);
                } else {
                    float h0 = tf32r(b0f), h1 = tf32r(b1f);
                    uint32_t bh0 = fbits(h0), bh1 = fbits(h1);
                    uint32_t bl0 = fbits(b0f - h0), bl1 = fbits(b1f - h1);
#pragma unroll
                    for (int mt = 0; mt < 2; mt++) {
                        float* ac = acc[mt * 8 + nt];
                        mma8(ac, ah[mt][0], ah[mt][1], ah[mt][2], ah[mt][3], bl0, bl1);
                        mma8(ac, al[mt][0], al[mt][1], al[mt][2], al[mt][3], bh0, bh1);
                        mma8(ac, ah[mt][0], ah[mt][1], ah[mt][2], ah[mt][3], bh0, bh1);
                    }
                }
            }
        }
    };

    stage(0, 0); cp_commit(); cp_wait0(); __syncthreads();
    for (int s = 0; s < nst; s++) {
        int buf = s & 1;
        if (s + 1 < nst) { stage(s + 1, buf ^ 1); cp_commit(); }
        comp(sA[buf], sB[buf]);
        if (s + 1 < nst) cp_wait0();
        __syncthreads();
    }

    const size_t HP = (size_t)Wp * Wp;
#pragma unroll
    for (int mt = 0; mt < 2; mt++)
#pragma unroll
        for (int nt = 0; nt < 8; nt++) {
            int c0 = nt * 8 + 2 * tq;
            float bv0 = bias[c0], bv1 = bias[c0 + 1];
            const float* A = acc[mt * 8 + nt];
#pragma unroll
            for (int h = 0; h < 2; h++) {
                int r = w * 32 + mt * 16 + g + h * 8;
                int gp2 = blockIdx.x * 128 + r;
                int qy = gp2 >> wsh, qx = gp2 & (Wp - 1);
                float v0 = A[2 * h] + bv0, v1 = A[2 * h + 1] + bv1;
                if (do_relu) { v0 = fmaxf(v0, 0.f); v1 = fmaxf(v1, 0.f); }
                if (ctype == 1) {
                    size_t o = (((size_t)b * 64 + c0) * (2 * Wp) + 2 * qy + dy) *
                               (size_t)(2 * Wp) + 2 * qx + dx;
                    out[o] = v0;
                    out[o + 4 * HP] = v1;
                } else {
                    size_t o = (((size_t)b * 64 + c0) * Wp + qy) * (size_t)Wp + qx;
                    out[o] = v0;
                    out[o + HP] = v1;
                }
            }
        }
}

__global__ void k_conv1(const float* __restrict__ x, const float* __restrict__ w,
                        const float* __restrict__ bias)
{
    __shared__ unsigned long long sw2[512];
    __shared__ float sb[64];
    const int tid = threadIdx.x;
    for (int i = tid; i < 512; i += 256) {
        int co2 = i >> 4, t = i & 15;
        sw2[i] = pk2(w[(2 * co2) * 16 + t], w[(2 * co2 + 1) * 16 + t]);
    }
    if (tid < 64) sb[tid] = bias[tid];
    __syncthreads();
    const int gid = blockIdx.x * 256 + tid;
    const int ox = gid & 255, oy = (gid >> 8) & 255, b = gid >> 16;
    const int iy0 = oy * 2 - 1, ix0 = ox * 2 - 1;
    const float* xb = x + (size_t)b * 262144;
    unsigned long long vp[16];
#pragma unroll
    for (int ky = 0; ky < 4; ky++)
#pragma unroll
        for (int kx = 0; kx < 4; kx++) {
            int iy = iy0 + ky, ix = ix0 + kx;
            float t = 0.f;
            if ((unsigned)iy < 512u && (unsigned)ix < 512u) t = xb[iy * 512 + ix];
            vp[ky * 4 + kx] = pk2(t, t);
        }
    float* ob = g_a1 + (size_t)b * 64 * 65536 + oy * 256 + ox;
#pragma unroll 4
    for (int co2 = 0; co2 < 32; co2++) {
        unsigned long long a2 = 0ull;
#pragma unroll
        for (int t = 0; t < 16; t++) ffma2(a2, vp[t], sw2[co2 * 16 + t]);
        float2 u = upk2(a2);
        ob[(size_t)(2 * co2) * 65536]     = fmaxf(u.x + sb[2 * co2], 0.f);
        ob[(size_t)(2 * co2 + 1) * 65536] = fmaxf(u.y + sb[2 * co2 + 1], 0.f);
    }
}

// final convT 64->1 + sigmoid. Grid MUST be (8,16,8).
__global__ __launch_bounds__(128) void k_cto(const float* __restrict__ w,
    const float* __restrict__ bias, float* __restrict__ out)
{
    __shared__ float s_t[2][18 * 35];
    __shared__ float s_w[1024];
    const int tid = threadIdx.x, tx = tid & 7, ty = tid >> 3;
    const int b = blockIdx.z;
    const int py0 = blockIdx.y * 16, qx0 = blockIdx.x * 32;
    const float* inb = g_a1 + (size_t)b * 64 * 65536;
    uint32_t st0 = (uint32_t)__cvta_generic_to_shared(&s_t[0][0]);
    for (int i = tid; i < 1024; i += 128) s_w[i] = w[i];

    auto stage = [&](int ci, int buf) {
        const float* ic = inb + (size_t)ci * 65536;
        for (int i = tid; i < 630; i += 128) {
            int r = i / 35, cl = i - r * 35;
            int iy = py0 - 1 + r, ix = qx0 - 1 + cl;
            bool ok = cl < 34 && (unsigned)iy < 256u && (unsigned)ix < 256u;
            cp4(st0 + (buf * 630 + i) * 4, ic + (ok ? iy * 256 + ix : 0), ok);
        }
    };

    unsigned long long acc[8];
#pragma unroll
    for (int i = 0; i < 8; i++) acc[i] = 0ull;

    stage(0, 0); cp_commit(); cp_wait0(); __syncthreads();
    for (int ci = 0; ci < 64; ci++) {
        int buf = ci & 1;
        if (ci + 1 < 64) { stage(ci + 1, buf ^ 1); cp_commit(); }
        const float* T = s_t[buf];
        float v[3][6];
#pragma unroll
        for (int r = 0; r < 3; r++)
#pragma unroll
            for (int c = 0; c < 6; c++) v[r][c] = T[(ty + r) * 35 + 4 * tx + c];
        unsigned long long vp[3][3][2];
#pragma unroll
        for (int rr = 0; rr < 3; rr++)
#pragma unroll
            for (int cc = 0; cc < 3; cc++)
#pragma unroll
                for (int jp = 0; jp < 2; jp++)
                    vp[rr][cc][jp] = pk2(v[rr][2 * jp + cc], v[rr][2 * jp + cc + 1]);
#pragma unroll
        for (int dy = 0; dy < 2; dy++)
#pragma unroll
            for (int dx = 0; dx < 2; dx++)
#pragma unroll
                for (int a = 0; a < 2; a++)
#pragma unroll
                    for (int bb = 0; bb < 2; bb++) {
                        float wv = s_w[ci * 16 + (1 - dy + 2 * a) * 4 + (1 - dx + 2 * bb)];
                        unsigned long long w2 = pk2(wv, wv);
                        int rr = 1 + dy - a, cc = 1 + dx - bb;
                        ffma2(acc[(dy * 2 + dx) * 2 + 0], vp[rr][cc][0], w2);
                        ffma2(acc[(dy * 2 + dx) * 2 + 1], vp[rr][cc][1], w2);
                    }
        if (ci + 1 < 64) cp_wait0();
        __syncthreads();
    }
    float bv = bias[0];
#pragma unroll
    for (int dy = 0; dy < 2; dy++)
#pragma unroll
        for (int dx = 0; dx < 2; dx++)
#pragma unroll
            for (int jp = 0; jp < 2; jp++) {
                float2 u = upk2(acc[(dy * 2 + dx) * 2 + jp]);
#pragma unroll
                for (int l = 0; l < 2; l++) {
                    int j = 2 * jp + l;
                    int oy = 2 * (py0 + ty) + dy, ox = 2 * (qx0 + 4 * tx + j) + dx;
                    float s = (l ? u.y : u.x) + bv;
                    s = 1.f / (1.f + expf(-s));
                    out[((size_t)b * 512 + oy) * 512 + ox] = s;
                }
            }
}

// VQ: 64 positions x 512 codes per block, FFMA2-blocked
__global__ __launch_bounds__(128) void k_vq(const float* __restrict__ cb)
{
    __shared__ float s_z[64 * 64];
    __shared__ float s_cb[2][64 * 66];
    __shared__ float s_z2[64];
    __shared__ float s_bd[64 * 8];
    __shared__ int   s_bk[64 * 8];
    __shared__ int   s_kf[64];
    const int tid = threadIdx.x;
    const int pos0 = blockIdx.x * 64;
    const int b = pos0 >> 12, hw0 = pos0 & 4095;
    const float* zb = g_z + (size_t)b * 262144;
    uint32_t sz0 = (uint32_t)__cvta_generic_to_shared(&s_z[0]);
    uint32_t sc0 = (uint32_t)__cvta_generic_to_shared(&s_cb[0][0]);

    for (int i = tid; i < 4096; i += 128) {
        int c = i >> 6, p = i & 63;
        cp4(sz0 + (c * 64 + p) * 4, zb + (size_t)c * 4096 + hw0 + p, true);
    }
    for (int i = tid; i < 4096; i += 128) {
        int code = i >> 6, c = i & 63;
        cp4(sc0 + (c * 66 + code) * 4, cb + i, true);
    }
    cp_commit(); cp_wait0(); __syncthreads();
    if (tid < 64) {
        float s = 0.f;
        for (int c = 0; c < 64; c++) { float t = s_z[c * 64 + tid]; s += t * t; }
        s_z2[tid] = s;
    }
    const int pg = tid & 15, cg = tid >> 4;
    float bd[4] = {FLT_MAX, FLT_MAX, FLT_MAX, FLT_MAX};
    int bk[4] = {0, 0, 0, 0};

    for (int chunk = 0; chunk < 8; chunk++) {
        int buf = chunk & 1;
        if (chunk < 7) {
            for (int i = tid; i < 4096; i += 128) {
                int code = i >> 6, c = i & 63;
                cp4(sc0 + ((buf ^ 1) * 4224 + c * 66 + code) * 4,
                    cb + (chunk + 1) * 4096 + i, true);
            }
            cp_commit();
        }
        unsigned long long acc[4][4];
#pragma unroll
        for (int j = 0; j < 4; j++)
#pragma unroll
            for (int jj = 0; jj < 4; jj++) acc[j][jj] = 0ull;
        const float* C = &s_cb[buf][0];
#pragma unroll 4
        for (int c = 0; c < 64; c++) {
            unsigned long long zz[4];
#pragma unroll
            for (int j = 0; j < 4; j++) {
                float zv = s_z[c * 64 + pg + 16 * j];
                zz[j] = pk2(zv, zv);
            }
            unsigned long long wv[4];
#pragma unroll
            for (int jj = 0; jj < 4; jj++)
                wv[jj] = *(const unsigned long long*)&C[c * 66 + cg * 8 + 2 * jj];
#pragma unroll
            for (int j = 0; j < 4; j++)
#pragma unroll
                for (int jj = 0; jj < 4; jj++) ffma2(acc[j][jj], zz[j], wv[jj]);
        }
#pragma unroll
        for (int jj = 0; jj < 4; jj++) {
            int k0 = chunk * 64 + cg * 8 + 2 * jj;
            float ea = g_e2[k0], ebv = g_e2[k0 + 1];
#pragma unroll
            for (int j = 0; j < 4; j++) {
                float2 d2 = upk2(acc[j][jj]);
                float d0 = ea - 2.f * d2.x, d1 = ebv - 2.f * d2.y;
                if (d0 < bd[j]) { bd[j] = d0; bk[j] = k0; }
                if (d1 < bd[j]) { bd[j] = d1; bk[j] = k0 + 1; }
            }
        }
        if (chunk < 7) cp_wait0();
        __syncthreads();
    }
#pragma unroll
    for (int j = 0; j < 4; j++) {
        int p = pg + 16 * j;
        s_bd[p * 8 + cg] = bd[j];
        s_bk[p * 8 + cg] = bk[j];
    }
    __syncthreads();
    if (tid < 64) {
        float best = FLT_MAX; int kb = 0;
        for (int c = 0; c < 8; c++) {
            float d = s_bd[tid * 8 + c]; int k = s_bk[tid * 8 + c];
            if (d < best || (d == best && k < kb)) { best = d; kb = k; }
        }
        g_dmin[pos0 + tid] = s_z2[tid] + best;
        s_kf[tid] = kb;
    }
    __syncthreads();
    float* zqb = g_zq + (size_t)b * 262144;
    for (int i = tid; i < 4096; i += 128) {
        int c = i >> 6, p = i & 63;
        zqb[(size_t)c * 4096 + hw0 + p] = cb[s_kf[p] * 64 + c];
    }
}

__global__ void k_loss(float* __restrict__ out_loss)
{
    __shared__ float sm[1024];
    int tid = threadIdx.x;
    float s = 0.f;
    for (int i = tid; i < 32768; i += 1024) s += g_dmin[i];
    sm[tid] = s;
    __syncthreads();
    for (int off = 512; off; off >>= 1) {
        if (tid < off) sm[tid] += sm[tid + off];
        __syncthreads();
    }
    if (tid == 0) out_loss[0] = sm[0] * (1.25f / 2097152.f);
}

extern "C" void kernel_launch(void* const* d_in, const int* in_sizes, int n_in,
                              void* d_out, int out_size)
{
    const float* x   = (const float*)d_in[0];
    const float* ew1 = (const float*)d_in[1];
    const float* eb1 = (const float*)d_in[2];
    const float* ew2 = (const float*)d_in[3];
    const float* eb2 = (const float*)d_in[4];
    const float* ew3 = (const float*)d_in[5];
    const float* eb3 = (const float*)d_in[6];
    const float* ew4 = (const float*)d_in[7];
    const float* eb4 = (const float*)d_in[8];
    const float* cb  = (const float*)d_in[9];
    const float* dw1 = (const float*)d_in[10];
    const float* db1 = (const float*)d_in[11];
    const float* tw1 = (const float*)d_in[12];
    const float* tb1 = (const float*)d_in[13];
    const float* tw2 = (const float*)d_in[14];
    const float* tb2 = (const float*)d_in[15];
    const float* tw3 = (const float*)d_in[16];
    const float* tb3 = (const float*)d_in[17];
    float* out = (float*)d_out;

    k_prep_all<<<5256, 64>>>(ew2, ew3, ew4, dw1, tw1, tw2, cb);
    k_conv1<<<2048, 256>>>(x, ew1, eb1);
    k_mconv<<<dim3(128, 8, 1), 128>>>(1, 1, eb2, 2, 256, 128, 7, 2, 1, 1); // conv2
    k_mconv<<<dim3(32, 8, 1),  128>>>(2, 2, eb3, 3, 128, 64, 6, 2, 1, 1);  // conv3
    k_mconv<<<dim3(32, 8, 1),  128>>>(3, 3, eb4, 4, 64, 64, 6, 0, 0, 1);   // enc4

    k_vq<<<512, 128>>>(cb);
    k_loss<<<1, 1024>>>(out + (out_size - 1));

    k_mconv<<<dim3(32, 8, 1),  128>>>(5, 4, db1, 6, 64, 64, 6, 0, 1, 0);   // dec1
    k_mconv<<<dim3(32, 8, 4),  128>>>(6, 5, tb1, 2, 64, 64, 6, 1, 1, 0);   // convT1
    k_mconv<<<dim3(128, 8, 4), 128>>>(2, 6, tb2, 1, 128, 128, 7, 1, 1, 0); // convT2
    k_cto<<<dim3(8, 16, 8), 128>>>(tw3, tb3, out);
}